// round 5
// baseline (speedup 1.0000x reference)
#include <cuda_runtime.h>
#include <cuda_bf16.h>
#include <cstdint>
#include <cstddef>

#define S_ 4
#define B_ 512
#define D_ 256
#define H_ 1024
#define T_ 50
#define M_ (S_*B_)          // 2048
#define PRED (M_*T_*D_)

// ---------------- device scratch (no allocation allowed) ----------------
__device__ __nv_bfloat16 g_Ahi[M_*D_],  g_Alo[M_*D_];      // layer-1 input (probe state, split)
__device__ __nv_bfloat16 g_H1hi[M_*H_], g_H1lo[M_*H_];
__device__ __nv_bfloat16 g_H2hi[M_*H_], g_H2lo[M_*H_];
__device__ float g_K1[M_*D_], g_K2[M_*D_], g_K3[M_*D_], g_Y[M_*D_];
// weights transposed to [N,K], split hi/lo bf16
__device__ __nv_bfloat16 g_W1hi[H_*D_], g_W1lo[H_*D_];
__device__ __nv_bfloat16 g_W2hi[H_*H_], g_W2lo[H_*H_];
__device__ __nv_bfloat16 g_W3hi[D_*H_], g_W3lo[D_*H_];

// ---------------- helpers ----------------
__device__ __forceinline__ uint32_t smem_u32(const void* p) {
    uint32_t a;
    asm("{ .reg .u64 t; cvta.to.shared.u64 t, %1; cvt.u32.u64 %0, t; }" : "=r"(a) : "l"(p));
    return a;
}
__device__ __forceinline__ void cp_async16(uint32_t saddr, const void* gaddr) {
    asm volatile("cp.async.cg.shared.global [%0], [%1], 16;" :: "r"(saddr), "l"(gaddr));
}
#define CP_COMMIT() asm volatile("cp.async.commit_group;" ::: "memory")
#define CP_WAIT2()  asm volatile("cp.async.wait_group 2;" ::: "memory")

// PDL controls (sm_90+ base ISA; no-ops when attribute absent)
__device__ __forceinline__ void gdc_wait()   { asm volatile("griddepcontrol.wait;" ::: "memory"); }
__device__ __forceinline__ void gdc_launch() { asm volatile("griddepcontrol.launch_dependents;" ::: "memory"); }

__device__ __forceinline__ void ldsm_x4(uint32_t* r, uint32_t addr) {
    asm volatile("ldmatrix.sync.aligned.m8n8.x4.shared.b16 {%0,%1,%2,%3}, [%4];"
                 : "=r"(r[0]), "=r"(r[1]), "=r"(r[2]), "=r"(r[3]) : "r"(addr));
}
__device__ __forceinline__ void mma16816(float* c, const uint32_t* a, uint32_t b0, uint32_t b1) {
    asm volatile("mma.sync.aligned.m16n8k16.row.col.f32.bf16.bf16.f32 "
                 "{%0,%1,%2,%3}, {%4,%5,%6,%7}, {%8,%9}, {%0,%1,%2,%3};"
                 : "+f"(c[0]), "+f"(c[1]), "+f"(c[2]), "+f"(c[3])
                 : "r"(a[0]), "r"(a[1]), "r"(a[2]), "r"(a[3]), "r"(b0), "r"(b1));
}

__device__ __forceinline__ float fast_tanh(float x) {
    float t = __expf(2.0f * x);
    return 1.0f - 2.0f / (t + 1.0f);
}
// split pair of floats into bf16x2 hi + bf16x2 lo words
__device__ __forceinline__ void split2(float a, float b, uint32_t& hi, uint32_t& lo) {
    __nv_bfloat16 ha = __float2bfloat16_rn(a), hb = __float2bfloat16_rn(b);
    __nv_bfloat162 ph; ph.x = ha; ph.y = hb;
    hi = *reinterpret_cast<uint32_t*>(&ph);
    __nv_bfloat162 pl = __floats2bfloat162_rn(a - __bfloat162float(ha), b - __bfloat162float(hb));
    lo = *reinterpret_cast<uint32_t*>(&pl);
}

// ---------------- tensor-core (HMMA) GEMM ----------------
// C[M=2048, NFULL] = A[M,KDIM] @ W^T  (W stored [NFULL,KDIM] hi/lo)
// flat chunk list over 3 split terms: term0 Ahi*Whi, term1 Ahi*Wlo, term2 Alo*Whi
// 4-stage cp.async pipeline, ONE __syncthreads per chunk.
// PDL: prologue prefetches static W tiles BEFORE griddepcontrol.wait, A tiles after.
// EPI 0: tanh -> split -> Ohi/Olo
// EPI 1: k=C+bias; Kout=k; probe=Y+alpha*dt*k -> split -> Ohi/Olo
// EPI 2: k4=C+bias; y'=Y+dt/6*(K1+2K2+2K3+k4); Y=y'; traj store; split(y') -> Ohi/Olo
template<int BM, int BN, int WM, int WN, int KDIM, int NFULL, int EPI>
__global__ void __launch_bounds__(256)
gemm_mma(const __nv_bfloat16* __restrict__ Ahi, const __nv_bfloat16* __restrict__ Alo,
         const __nv_bfloat16* __restrict__ Whi, const __nv_bfloat16* __restrict__ Wlo,
         const float* __restrict__ bias,
         __nv_bfloat16* __restrict__ Ohi, __nv_bfloat16* __restrict__ Olo,
         float* __restrict__ Kout,
         const float* __restrict__ K1c, const float* __restrict__ K2c, const float* __restrict__ K3c,
         float* __restrict__ Ybuf, float* __restrict__ dout,
         const float* __restrict__ tarr, int step, float alpha)
{
    constexpr int WARPS_M = BM / WM;
    constexpr int KC64    = KDIM / 64;          // 64-elem K chunks per term
    constexpr int NC      = 3 * KC64;           // flat chunk count (3 split terms)
    constexpr int STAGE   = (BM + BN) * 128;    // bytes per pipeline stage
    constexpr int MI = WM / 16, NJ = WN / 8, NJJ = WN / 16;

    extern __shared__ __align__(128) char sm[];
    const uint32_t smb = smem_u32(sm);

    const int tid  = threadIdx.x;
    const int wid  = tid >> 5, lane = tid & 31;
    const int wm   = wid % WARPS_M, wn = wid / WARPS_M;
    const int bm   = blockIdx.y * BM;
    const int bn   = blockIdx.x * BN;

    float acc[MI][NJ][4];
    #pragma unroll
    for (int i = 0; i < MI; i++)
        #pragma unroll
        for (int j = 0; j < NJ; j++)
            #pragma unroll
            for (int q = 0; q < 4; q++) acc[i][j][q] = 0.0f;

    // W-tile loader (weights are static — safe pre-sync)
    auto load_W = [&](int c, int slot) {
        const int term = c / KC64;
        const int k0   = (c % KC64) * 64;
        const __nv_bfloat16* __restrict__ Ws = (term == 1) ? Wlo : Whi;
        const uint32_t sb = smb + (uint32_t)slot * STAGE + BM * 128;
        #pragma unroll
        for (int i = tid; i < BN * 8; i += 256) {
            const int row = i >> 3, seg = i & 7;
            cp_async16(sb + (uint32_t)row * 128 + (uint32_t)((seg ^ (row & 7)) << 4),
                       Ws + (size_t)(bn + row) * KDIM + k0 + seg * 8);
        }
    };
    // A-tile loader (depends on prior kernel — post-sync only)
    auto load_A = [&](int c, int slot) {
        const int term = c / KC64;
        const int k0   = (c % KC64) * 64;
        const __nv_bfloat16* __restrict__ As = (term < 2) ? Ahi : Alo;
        const uint32_t sb = smb + (uint32_t)slot * STAGE;
        #pragma unroll
        for (int i = tid; i < BM * 8; i += 256) {
            const int row = i >> 3, seg = i & 7;
            cp_async16(sb + (uint32_t)row * 128 + (uint32_t)((seg ^ (row & 7)) << 4),
                       As + (size_t)(bm + row) * KDIM + k0 + seg * 8);
        }
    };

    // prologue: prefetch W for 3 stages while predecessor still runs, then sync, then A
    load_W(0, 0); load_W(1, 1); load_W(2, 2);
    gdc_wait();
    load_A(0, 0); CP_COMMIT();        // group0 = {W0,W1,W2,A0}
    load_A(1, 1); CP_COMMIT();        // group1 = {A1}
    load_A(2, 2); CP_COMMIT();        // group2 = {A2}

    const int oct = lane >> 3, lr = lane & 7;

    for (int c = 0; c < NC; c++) {
        CP_WAIT2();            // stage c data ready
        __syncthreads();       // all warps also done reading stage (c-1)&3
        if (c + 3 < NC) {      // overwrite (c-1)&3 — safe post-sync
            load_A(c + 3, (c + 3) & 3);
            load_W(c + 3, (c + 3) & 3);
        }
        CP_COMMIT();

        const uint32_t sb = smb + (uint32_t)(c & 3) * STAGE;
        const uint32_t Ab = sb;
        const uint32_t Bb = sb + BM * 128;

        #pragma unroll
        for (int t = 0; t < 4; t++) {
            uint32_t af[MI][4], bf[NJJ][4];
            #pragma unroll
            for (int i = 0; i < MI; i++) {
                const int row = wm * WM + i * 16 + (oct & 1) * 8 + lr;
                const int ks  = t * 2 + (oct >> 1);
                ldsm_x4(af[i], Ab + (uint32_t)row * 128 + (uint32_t)(((ks ^ (row & 7)) << 4)));
            }
            #pragma unroll
            for (int jj = 0; jj < NJJ; jj++) {
                const int row = wn * WN + jj * 16 + (oct >> 1) * 8 + lr;
                const int ks  = t * 2 + (oct & 1);
                ldsm_x4(bf[jj], Bb + (uint32_t)row * 128 + (uint32_t)(((ks ^ (row & 7)) << 4)));
            }
            #pragma unroll
            for (int i = 0; i < MI; i++)
                #pragma unroll
                for (int j = 0; j < NJ; j++)
                    mma16816(acc[i][j], af[i], bf[j >> 1][(j & 1) * 2], bf[j >> 1][(j & 1) * 2 + 1]);
        }
    }

    gdc_launch();   // successor may start its W-prefetch while we run the epilogue

    // ---------------- fused epilogue ----------------
    float dt = 0.0f;
    if (EPI != 0) dt = tarr[step + 1] - tarr[step];
    const float ad = alpha * dt;
    const float c6 = dt * (1.0f / 6.0f);

    const int r00   = bm + wm * WM + (lane >> 2);
    const int cbase = bn + wn * WN + (lane & 3) * 2;

    #pragma unroll
    for (int i = 0; i < MI; i++) {
        #pragma unroll
        for (int j = 0; j < NJ; j++) {
            const int cc = cbase + j * 8;
            const float2 bs = *(const float2*)&bias[cc];
            const int rows[2] = { r00 + i * 16, r00 + i * 16 + 8 };
            #pragma unroll
            for (int h = 0; h < 2; h++) {
                float v0 = acc[i][j][2*h + 0] + bs.x;
                float v1 = acc[i][j][2*h + 1] + bs.y;
                const size_t idx = (size_t)rows[h] * NFULL + cc;
                if (EPI == 0) {
                    v0 = fast_tanh(v0); v1 = fast_tanh(v1);
                    uint32_t hi, lo; split2(v0, v1, hi, lo);
                    *(uint32_t*)(Ohi + idx) = hi;
                    *(uint32_t*)(Olo + idx) = lo;
                } else if (EPI == 1) {
                    *(float2*)&Kout[idx] = make_float2(v0, v1);
                    const float2 y = *(const float2*)&Ybuf[idx];
                    const float p0 = fmaf(ad, v0, y.x);
                    const float p1 = fmaf(ad, v1, y.y);
                    uint32_t hi, lo; split2(p0, p1, hi, lo);
                    *(uint32_t*)(Ohi + idx) = hi;
                    *(uint32_t*)(Olo + idx) = lo;
                } else {
                    const float2 y  = *(const float2*)&Ybuf[idx];
                    const float2 k1 = *(const float2*)&K1c[idx];
                    const float2 k2 = *(const float2*)&K2c[idx];
                    const float2 k3 = *(const float2*)&K3c[idx];
                    const float y0 = y.x + c6 * (k1.x + 2.0f*k2.x + 2.0f*k3.x + v0);
                    const float y1 = y.y + c6 * (k1.y + 2.0f*k2.y + 2.0f*k3.y + v1);
                    *(float2*)&Ybuf[idx] = make_float2(y0, y1);
                    *(float2*)&dout[((size_t)rows[h] * T_ + step + 1) * NFULL + cc] =
                        make_float2(y0, y1);
                    uint32_t hi, lo; split2(y0, y1, hi, lo);
                    *(uint32_t*)(Ohi + idx) = hi;
                    *(uint32_t*)(Olo + idx) = lo;
                }
            }
        }
    }
}

// ---------------- weight prep: W[K,N] fp32 -> Wt[N,K] bf16 hi/lo ----------------
__global__ void prep_w(const float* __restrict__ W,
                       __nv_bfloat16* __restrict__ Whi, __nv_bfloat16* __restrict__ Wlo,
                       int K, int N)
{
    __shared__ float s[32][33];
    int k0 = blockIdx.y * 32, n0 = blockIdx.x * 32;
    int tx = threadIdx.x, ty = threadIdx.y;   // (32,8)
    #pragma unroll
    for (int r = 0; r < 4; r++)
        s[ty + r*8][tx] = W[(size_t)(k0 + ty + r*8) * N + n0 + tx];
    __syncthreads();
    #pragma unroll
    for (int r = 0; r < 4; r++) {
        int n = n0 + ty + r*8;
        float v = s[tx][ty + r*8];
        __nv_bfloat16 h = __float2bfloat16_rn(v);
        Whi[(size_t)n * K + k0 + tx] = h;
        Wlo[(size_t)n * K + k0 + tx] = __float2bfloat16_rn(v - __bfloat162float(h));
    }
}

__global__ void init_k(const float* __restrict__ fp, float* __restrict__ out) {
    int i = blockIdx.x * blockDim.x + threadIdx.x;
    if (i < M_ * D_) {
        float v = fp[i];
        g_Y[i] = v;
        __nv_bfloat16 h = __float2bfloat16_rn(v);
        g_Ahi[i] = h;
        g_Alo[i] = __float2bfloat16_rn(v - __bfloat162float(h));
        int m = i >> 8, d = i & 255;
        out[(size_t)m * T_ * D_ + d] = v;
    }
}

__global__ void tail_k(float* __restrict__ out, int out_size) {
    int i = PRED + blockIdx.x * blockDim.x + threadIdx.x;
    if (i < out_size) out[i] = 0.0f;
}

// ---------------- host ----------------
template<typename T> static T* sym(const void* s) {
    void* p = nullptr;
    cudaGetSymbolAddress(&p, s);
    return (T*)p;
}

using GemmFn = void (*)(const __nv_bfloat16*, const __nv_bfloat16*,
                        const __nv_bfloat16*, const __nv_bfloat16*,
                        const float*, __nv_bfloat16*, __nv_bfloat16*, float*,
                        const float*, const float*, const float*,
                        float*, float*, const float*, int, float);

static void launch_pdl(GemmFn k, dim3 g, dim3 b, size_t smem,
                       const __nv_bfloat16* Ahi, const __nv_bfloat16* Alo,
                       const __nv_bfloat16* Whi, const __nv_bfloat16* Wlo,
                       const float* bias, __nv_bfloat16* Ohi, __nv_bfloat16* Olo,
                       float* Kout, const float* K1c, const float* K2c, const float* K3c,
                       float* Ybuf, float* dout, const float* tarr, int step, float alpha)
{
    cudaLaunchConfig_t cfg = {};
    cfg.gridDim = g; cfg.blockDim = b; cfg.dynamicSmemBytes = smem; cfg.stream = 0;
    cudaLaunchAttribute at[1];
    at[0].id = cudaLaunchAttributeProgrammaticStreamSerialization;
    at[0].val.programmaticStreamSerializationAllowed = 1;
    cfg.attrs = at; cfg.numAttrs = 1;
    cudaLaunchKernelEx(&cfg, k, Ahi, Alo, Whi, Wlo, bias, Ohi, Olo,
                       Kout, K1c, K2c, K3c, Ybuf, dout, tarr, step, alpha);
}

extern "C" void kernel_launch(void* const* d_in, const int* in_sizes, int n_in,
                              void* d_out, int out_size)
{
    const float* fp   = (const float*)d_in[0];
    const float* tarr = (const float*)d_in[1];
    const float* W1   = (const float*)d_in[2];
    const float* b1   = (const float*)d_in[3];
    const float* W2   = (const float*)d_in[4];
    const float* b2   = (const float*)d_in[5];
    const float* W3   = (const float*)d_in[6];
    const float* b3   = (const float*)d_in[7];
    float* out = (float*)d_out;
    (void)in_sizes; (void)n_in;

    __nv_bfloat16 *Ahi = sym<__nv_bfloat16>(g_Ahi), *Alo = sym<__nv_bfloat16>(g_Alo);
    __nv_bfloat16 *H1h = sym<__nv_bfloat16>(g_H1hi), *H1l = sym<__nv_bfloat16>(g_H1lo);
    __nv_bfloat16 *H2h = sym<__nv_bfloat16>(g_H2hi), *H2l = sym<__nv_bfloat16>(g_H2lo);
    __nv_bfloat16 *W1h = sym<__nv_bfloat16>(g_W1hi), *W1l = sym<__nv_bfloat16>(g_W1lo);
    __nv_bfloat16 *W2h = sym<__nv_bfloat16>(g_W2hi), *W2l = sym<__nv_bfloat16>(g_W2lo);
    __nv_bfloat16 *W3h = sym<__nv_bfloat16>(g_W3hi), *W3l = sym<__nv_bfloat16>(g_W3lo);
    float *K1 = sym<float>(g_K1), *K2 = sym<float>(g_K2), *K3 = sym<float>(g_K3);
    float *Y  = sym<float>(g_Y);

    GemmFn kL1 = gemm_mma<128,128,32,64, D_,H_,0>;
    GemmFn kL2 = gemm_mma<128,128,32,64, H_,H_,0>;
    GemmFn kL3a = gemm_mma<64,64,32,16, H_,D_,1>;
    GemmFn kL3b = gemm_mma<64,64,32,16, H_,D_,2>;

    // SMEM: 4 stages of (BM+BN)*128 bytes
    constexpr int SM_H = 4 * (128 + 128) * 128;  // 131072
    constexpr int SM_D = 4 * (64 + 64) * 128;    //  65536
    cudaFuncSetAttribute((const void*)kL1,  cudaFuncAttributeMaxDynamicSharedMemorySize, SM_H);
    cudaFuncSetAttribute((const void*)kL2,  cudaFuncAttributeMaxDynamicSharedMemorySize, SM_H);
    cudaFuncSetAttribute((const void*)kL3a, cudaFuncAttributeMaxDynamicSharedMemorySize, SM_D);
    cudaFuncSetAttribute((const void*)kL3b, cudaFuncAttributeMaxDynamicSharedMemorySize, SM_D);

    // small kernels first so profiler skip-count lands on a GEMM
    init_k<<<(M_*D_ + 255)/256, 256>>>(fp, out);
    if (out_size > PRED)
        tail_k<<<(out_size - PRED + 255)/256, 256>>>(out, out_size);
    prep_w<<<dim3(H_/32, D_/32), dim3(32,8)>>>(W1, W1h, W1l, D_, H_);
    prep_w<<<dim3(H_/32, H_/32), dim3(32,8)>>>(W2, W2h, W2l, H_, H_);
    prep_w<<<dim3(D_/32, H_/32), dim3(32,8)>>>(W3, W3h, W3l, H_, D_);

    dim3 blk(256);
    dim3 gH(H_/128, M_/128);  // (8,16) = 128 CTAs
    dim3 gD(D_/64,  M_/64);   // (4,32) = 128 CTAs

    for (int s = 0; s < T_ - 1; s++) {
        // eval 1: f(Y)
        launch_pdl(kL1, gH, blk, SM_H, Ahi, Alo, W1h, W1l, b1, H1h, H1l,
                   nullptr, nullptr, nullptr, nullptr, nullptr, nullptr, tarr, s, 0.f);
        launch_pdl(kL2, gH, blk, SM_H, H1h, H1l, W2h, W2l, b2, H2h, H2l,
                   nullptr, nullptr, nullptr, nullptr, nullptr, nullptr, tarr, s, 0.f);
        launch_pdl(kL3a, gD, blk, SM_D, H2h, H2l, W3h, W3l, b3, Ahi, Alo,
                   K1, nullptr, nullptr, nullptr, Y, nullptr, tarr, s, 0.5f);
        // eval 2
        launch_pdl(kL1, gH, blk, SM_H, Ahi, Alo, W1h, W1l, b1, H1h, H1l,
                   nullptr, nullptr, nullptr, nullptr, nullptr, nullptr, tarr, s, 0.f);
        launch_pdl(kL2, gH, blk, SM_H, H1h, H1l, W2h, W2l, b2, H2h, H2l,
                   nullptr, nullptr, nullptr, nullptr, nullptr, nullptr, tarr, s, 0.f);
        launch_pdl(kL3a, gD, blk, SM_D, H2h, H2l, W3h, W3l, b3, Ahi, Alo,
                   K2, nullptr, nullptr, nullptr, Y, nullptr, tarr, s, 0.5f);
        // eval 3
        launch_pdl(kL1, gH, blk, SM_H, Ahi, Alo, W1h, W1l, b1, H1h, H1l,
                   nullptr, nullptr, nullptr, nullptr, nullptr, nullptr, tarr, s, 0.f);
        launch_pdl(kL2, gH, blk, SM_H, H1h, H1l, W2h, W2l, b2, H2h, H2l,
                   nullptr, nullptr, nullptr, nullptr, nullptr, nullptr, tarr, s, 0.f);
        launch_pdl(kL3a, gD, blk, SM_D, H2h, H2l, W3h, W3l, b3, Ahi, Alo,
                   K3, nullptr, nullptr, nullptr, Y, nullptr, tarr, s, 1.0f);
        // eval 4 + RK4 combine fused
        launch_pdl(kL1, gH, blk, SM_H, Ahi, Alo, W1h, W1l, b1, H1h, H1l,
                   nullptr, nullptr, nullptr, nullptr, nullptr, nullptr, tarr, s, 0.f);
        launch_pdl(kL2, gH, blk, SM_H, H1h, H1l, W2h, W2l, b2, H2h, H2l,
                   nullptr, nullptr, nullptr, nullptr, nullptr, nullptr, tarr, s, 0.f);
        launch_pdl(kL3b, gD, blk, SM_D, H2h, H2l, W3h, W3l, b3, Ahi, Alo,
                   nullptr, K1, K2, K3, Y, out, tarr, s, 0.f);
    }
}

// round 6
// speedup vs baseline: 1.9590x; 1.9590x over previous
#include <cuda_runtime.h>
#include <cuda_fp16.h>
#include <cstdint>
#include <cstddef>

#define S_ 4
#define B_ 512
#define D_ 256
#define H_ 1024
#define T_ 50
#define M_ (S_*B_)          // 2048
#define PRED (M_*T_*D_)

// ---------------- device scratch (no allocation allowed) ----------------
__device__ __half g_A [M_*D_];       // layer-1 input (probe state), fp16
__device__ __half g_H1[M_*H_];
__device__ __half g_H2[M_*H_];
__device__ float g_K1[M_*D_], g_K2[M_*D_], g_K3[M_*D_], g_Y[M_*D_];
// weights transposed to [N,K], split into two fp16 terms (W = Wh + Wl, exact to ~2^-22)
__device__ __half g_W1h[H_*D_], g_W1l[H_*D_];
__device__ __half g_W2h[H_*H_], g_W2l[H_*H_];
__device__ __half g_W3h[D_*H_], g_W3l[D_*H_];

// ---------------- helpers ----------------
__device__ __forceinline__ uint32_t smem_u32(const void* p) {
    uint32_t a;
    asm("{ .reg .u64 t; cvta.to.shared.u64 t, %1; cvt.u32.u64 %0, t; }" : "=r"(a) : "l"(p));
    return a;
}
__device__ __forceinline__ void cp_async16(uint32_t saddr, const void* gaddr) {
    asm volatile("cp.async.cg.shared.global [%0], [%1], 16;" :: "r"(saddr), "l"(gaddr));
}
#define CP_COMMIT() asm volatile("cp.async.commit_group;" ::: "memory")
#define CP_WAIT1()  asm volatile("cp.async.wait_group 1;" ::: "memory")

__device__ __forceinline__ void ldsm_x4(uint32_t* r, uint32_t addr) {
    asm volatile("ldmatrix.sync.aligned.m8n8.x4.shared.b16 {%0,%1,%2,%3}, [%4];"
                 : "=r"(r[0]), "=r"(r[1]), "=r"(r[2]), "=r"(r[3]) : "r"(addr));
}
__device__ __forceinline__ void mma16816(float* c, const uint32_t* a, uint32_t b0, uint32_t b1) {
    asm volatile("mma.sync.aligned.m16n8k16.row.col.f32.f16.f16.f32 "
                 "{%0,%1,%2,%3}, {%4,%5,%6,%7}, {%8,%9}, {%0,%1,%2,%3};"
                 : "+f"(c[0]), "+f"(c[1]), "+f"(c[2]), "+f"(c[3])
                 : "r"(a[0]), "r"(a[1]), "r"(a[2]), "r"(a[3]), "r"(b0), "r"(b1));
}

__device__ __forceinline__ float fast_tanh(float x) {
    float t = __expf(2.0f * x);
    return 1.0f - 2.0f / (t + 1.0f);
}
__device__ __forceinline__ uint32_t pack_h2(float a, float b) {
    __half2 h = __floats2half2_rn(a, b);
    return *reinterpret_cast<uint32_t*>(&h);
}

// ---------------- tensor-core (HMMA fp16) GEMM ----------------
// C[M=2048, NFULL] = A[M,KDIM] @ (Wh+Wl)^T   (W stored [NFULL,KDIM] fp16 hi/lo)
// per-chunk stage = [A(BM rows) | Wh(BN rows) | Wl(BN rows)], 64 K-elems each.
// 3-stage cp.async pipeline, one __syncthreads + wait_group 1 per chunk.
// EPI 0: tanh -> fp16 -> O
// EPI 1: k=C+bias; Kout=k; probe=Y+alpha*dt*k -> fp16 -> O
// EPI 2: k4=C+bias; y'=Y+dt/6*(K1+2K2+2K3+k4); Y=y'; traj store; fp16(y') -> O
template<int BM, int BN, int WM, int WN, int KDIM, int NFULL, int EPI>
__global__ void __launch_bounds__(256)
gemm_mma(const __half* __restrict__ A,
         const __half* __restrict__ Wh, const __half* __restrict__ Wl,
         const float* __restrict__ bias,
         __half* __restrict__ O,
         float* __restrict__ Kout,
         const float* __restrict__ K1c, const float* __restrict__ K2c, const float* __restrict__ K3c,
         float* __restrict__ Ybuf, float* __restrict__ dout,
         const float* __restrict__ tarr, int step, float alpha)
{
    constexpr int WARPS_M = BM / WM;
    constexpr int NC      = KDIM / 64;          // 64-elem K chunks
    constexpr int STAGE   = (BM + 2 * BN) * 128;
    constexpr int MI = WM / 16, NJ = WN / 8, NJJ = WN / 16;

    extern __shared__ __align__(128) char sm[];
    const uint32_t smb = smem_u32(sm);

    const int tid  = threadIdx.x;
    const int wid  = tid >> 5, lane = tid & 31;
    const int wm   = wid % WARPS_M, wn = wid / WARPS_M;
    const int bm   = blockIdx.y * BM;
    const int bn   = blockIdx.x * BN;

    float acc[MI][NJ][4];
    #pragma unroll
    for (int i = 0; i < MI; i++)
        #pragma unroll
        for (int j = 0; j < NJ; j++)
            #pragma unroll
            for (int q = 0; q < 4; q++) acc[i][j][q] = 0.0f;

    auto load_chunk = [&](int c, int slot) {
        const int k0 = c * 64;
        const uint32_t sb = smb + (uint32_t)slot * STAGE;
        #pragma unroll
        for (int i = tid; i < (BM + 2 * BN) * 8; i += 256) {
            const int seg = i & 7;
            const __half* src;
            uint32_t base;
            if (i < BM * 8) {
                const int row = i >> 3;
                src  = A + (size_t)(bm + row) * KDIM + k0 + seg * 8;
                base = sb + (uint32_t)row * 128;
            } else if (i < (BM + BN) * 8) {
                const int row = (i - BM * 8) >> 3;
                src  = Wh + (size_t)(bn + row) * KDIM + k0 + seg * 8;
                base = sb + (uint32_t)(BM + row) * 128;
            } else {
                const int row = (i - (BM + BN) * 8) >> 3;
                src  = Wl + (size_t)(bn + row) * KDIM + k0 + seg * 8;
                base = sb + (uint32_t)(BM + BN + row) * 128;
            }
            const int row8 = (base >> 7) & 7;   // swizzle uses row within 8-row block
            cp_async16(base + (uint32_t)((seg ^ row8) << 4), src);
        }
    };

    // prologue: 2 stages in flight
    load_chunk(0, 0); CP_COMMIT();
    load_chunk(1, 1); CP_COMMIT();

    const int oct = lane >> 3, lr = lane & 7;

    for (int c = 0; c < NC; c++) {
        CP_WAIT1();            // chunk c complete (chunk c+1 may be in flight)
        __syncthreads();       // all warps done reading stage (c-1)%3
        if (c + 2 < NC) load_chunk(c + 2, (c + 2) % 3);
        CP_COMMIT();           // commit every iter (possibly empty) to keep group algebra uniform

        const uint32_t sb  = smb + (uint32_t)(c % 3) * STAGE;
        const uint32_t Ab  = sb;
        const uint32_t Bhb = sb + BM * 128;
        const uint32_t Blb = sb + (BM + BN) * 128;

        #pragma unroll
        for (int t = 0; t < 4; t++) {
            uint32_t af[MI][4], bh[NJJ][4], bl[NJJ][4];
            #pragma unroll
            for (int i = 0; i < MI; i++) {
                const int row = wm * WM + i * 16 + (oct & 1) * 8 + lr;
                const int ks  = t * 2 + (oct >> 1);
                ldsm_x4(af[i], Ab + (uint32_t)row * 128 + (uint32_t)((ks ^ (row & 7)) << 4));
            }
            #pragma unroll
            for (int jj = 0; jj < NJJ; jj++) {
                const int row = wn * WN + jj * 16 + (oct >> 1) * 8 + lr;
                const int ks  = t * 2 + (oct & 1);
                const uint32_t off = (uint32_t)row * 128 + (uint32_t)((ks ^ (row & 7)) << 4);
                ldsm_x4(bh[jj], Bhb + off);
                ldsm_x4(bl[jj], Blb + off);
            }
            #pragma unroll
            for (int i = 0; i < MI; i++)
                #pragma unroll
                for (int j = 0; j < NJ; j++) {
                    mma16816(acc[i][j], af[i], bh[j >> 1][(j & 1) * 2], bh[j >> 1][(j & 1) * 2 + 1]);
                    mma16816(acc[i][j], af[i], bl[j >> 1][(j & 1) * 2], bl[j >> 1][(j & 1) * 2 + 1]);
                }
        }
    }

    // ---------------- fused epilogue ----------------
    float dt = 0.0f;
    if (EPI != 0) dt = tarr[step + 1] - tarr[step];
    const float ad = alpha * dt;
    const float c6 = dt * (1.0f / 6.0f);

    const int r00   = bm + wm * WM + (lane >> 2);
    const int cbase = bn + wn * WN + (lane & 3) * 2;

    #pragma unroll
    for (int i = 0; i < MI; i++) {
        #pragma unroll
        for (int j = 0; j < NJ; j++) {
            const int cc = cbase + j * 8;
            const float2 bs = *(const float2*)&bias[cc];
            const int rows[2] = { r00 + i * 16, r00 + i * 16 + 8 };
            #pragma unroll
            for (int h = 0; h < 2; h++) {
                float v0 = acc[i][j][2*h + 0] + bs.x;
                float v1 = acc[i][j][2*h + 1] + bs.y;
                const size_t idx = (size_t)rows[h] * NFULL + cc;
                if (EPI == 0) {
                    v0 = fast_tanh(v0); v1 = fast_tanh(v1);
                    *(uint32_t*)(O + idx) = pack_h2(v0, v1);
                } else if (EPI == 1) {
                    *(float2*)&Kout[idx] = make_float2(v0, v1);
                    const float2 y = *(const float2*)&Ybuf[idx];
                    *(uint32_t*)(O + idx) = pack_h2(fmaf(ad, v0, y.x), fmaf(ad, v1, y.y));
                } else {
                    const float2 y  = *(const float2*)&Ybuf[idx];
                    const float2 k1 = *(const float2*)&K1c[idx];
                    const float2 k2 = *(const float2*)&K2c[idx];
                    const float2 k3 = *(const float2*)&K3c[idx];
                    const float y0 = y.x + c6 * (k1.x + 2.0f*k2.x + 2.0f*k3.x + v0);
                    const float y1 = y.y + c6 * (k1.y + 2.0f*k2.y + 2.0f*k3.y + v1);
                    *(float2*)&Ybuf[idx] = make_float2(y0, y1);
                    *(float2*)&dout[((size_t)rows[h] * T_ + step + 1) * NFULL + cc] =
                        make_float2(y0, y1);
                    *(uint32_t*)(O + idx) = pack_h2(y0, y1);
                }
            }
        }
    }
}

// ---------------- weight prep: W[K,N] fp32 -> Wt[N,K] fp16 hi/lo ----------------
__global__ void prep_w(const float* __restrict__ W,
                       __half* __restrict__ Wh, __half* __restrict__ Wl,
                       int K, int N)
{
    __shared__ float s[32][33];
    int k0 = blockIdx.y * 32, n0 = blockIdx.x * 32;
    int tx = threadIdx.x, ty = threadIdx.y;   // (32,8)
    #pragma unroll
    for (int r = 0; r < 4; r++)
        s[ty + r*8][tx] = W[(size_t)(k0 + ty + r*8) * N + n0 + tx];
    __syncthreads();
    #pragma unroll
    for (int r = 0; r < 4; r++) {
        int n = n0 + ty + r*8;
        float v = s[tx][ty + r*8];
        __half h = __float2half_rn(v);
        Wh[(size_t)n * K + k0 + tx] = h;
        Wl[(size_t)n * K + k0 + tx] = __float2half_rn(v - __half2float(h));
    }
}

__global__ void init_k(const float* __restrict__ fp, float* __restrict__ out) {
    int i = blockIdx.x * blockDim.x + threadIdx.x;
    if (i < M_ * D_) {
        float v = fp[i];
        g_Y[i] = v;
        g_A[i] = __float2half_rn(v);
        int m = i >> 8, d = i & 255;
        out[(size_t)m * T_ * D_ + d] = v;
    }
}

__global__ void tail_k(float* __restrict__ out, int out_size) {
    int i = PRED + blockIdx.x * blockDim.x + threadIdx.x;
    if (i < out_size) out[i] = 0.0f;
}

// ---------------- host ----------------
template<typename T> static T* sym(const void* s) {
    void* p = nullptr;
    cudaGetSymbolAddress(&p, s);
    return (T*)p;
}

extern "C" void kernel_launch(void* const* d_in, const int* in_sizes, int n_in,
                              void* d_out, int out_size)
{
    const float* fp   = (const float*)d_in[0];
    const float* tarr = (const float*)d_in[1];
    const float* W1   = (const float*)d_in[2];
    const float* b1   = (const float*)d_in[3];
    const float* W2   = (const float*)d_in[4];
    const float* b2   = (const float*)d_in[5];
    const float* W3   = (const float*)d_in[6];
    const float* b3   = (const float*)d_in[7];
    float* out = (float*)d_out;
    (void)in_sizes; (void)n_in;

    __half *A   = sym<__half>(g_A);
    __half *H1  = sym<__half>(g_H1), *H2 = sym<__half>(g_H2);
    __half *W1h = sym<__half>(g_W1h), *W1l = sym<__half>(g_W1l);
    __half *W2h = sym<__half>(g_W2h), *W2l = sym<__half>(g_W2l);
    __half *W3h = sym<__half>(g_W3h), *W3l = sym<__half>(g_W3l);
    float *K1 = sym<float>(g_K1), *K2 = sym<float>(g_K2), *K3 = sym<float>(g_K3);
    float *Y  = sym<float>(g_Y);

    // SMEM: 3 stages of (BM + 2*BN)*128 bytes
    constexpr int SM_H = 3 * (128 + 2*128) * 128;  // 147456 (H layers)
    constexpr int SM_D = 3 * (64 + 2*64) * 128;    //  73728 (L3)
    cudaFuncSetAttribute((const void*)gemm_mma<128,128,32,64, D_,H_,0>,
                         cudaFuncAttributeMaxDynamicSharedMemorySize, SM_H);
    cudaFuncSetAttribute((const void*)gemm_mma<128,128,32,64, H_,H_,0>,
                         cudaFuncAttributeMaxDynamicSharedMemorySize, SM_H);
    cudaFuncSetAttribute((const void*)gemm_mma<64,64,32,16, H_,D_,1>,
                         cudaFuncAttributeMaxDynamicSharedMemorySize, SM_D);
    cudaFuncSetAttribute((const void*)gemm_mma<64,64,32,16, H_,D_,2>,
                         cudaFuncAttributeMaxDynamicSharedMemorySize, SM_D);

    // small kernels first (also shifts profiler capture toward a GEMM)
    init_k<<<(M_*D_ + 255)/256, 256>>>(fp, out);
    if (out_size > PRED)
        tail_k<<<(out_size - PRED + 255)/256, 256>>>(out, out_size);
    prep_w<<<dim3(H_/32, D_/32), dim3(32,8)>>>(W1, W1h, W1l, D_, H_);
    prep_w<<<dim3(H_/32, H_/32), dim3(32,8)>>>(W2, W2h, W2l, H_, H_);
    prep_w<<<dim3(D_/32, H_/32), dim3(32,8)>>>(W3, W3h, W3l, H_, D_);

    dim3 blk(256);
    dim3 gH(H_/128, M_/128);  // (8,16) = 128 CTAs
    dim3 gD(D_/64,  M_/64);   // (4,32) = 128 CTAs

    for (int s = 0; s < T_ - 1; s++) {
        // eval 1: f(Y)
        gemm_mma<128,128,32,64, D_,H_,0><<<gH, blk, SM_H>>>(A, W1h, W1l, b1, H1,
            nullptr, nullptr, nullptr, nullptr, nullptr, nullptr, tarr, s, 0.f);
        gemm_mma<128,128,32,64, H_,H_,0><<<gH, blk, SM_H>>>(H1, W2h, W2l, b2, H2,
            nullptr, nullptr, nullptr, nullptr, nullptr, nullptr, tarr, s, 0.f);
        gemm_mma<64,64,32,16, H_,D_,1><<<gD, blk, SM_D>>>(H2, W3h, W3l, b3, A,
            K1, nullptr, nullptr, nullptr, Y, nullptr, tarr, s, 0.5f);
        // eval 2
        gemm_mma<128,128,32,64, D_,H_,0><<<gH, blk, SM_H>>>(A, W1h, W1l, b1, H1,
            nullptr, nullptr, nullptr, nullptr, nullptr, nullptr, tarr, s, 0.f);
        gemm_mma<128,128,32,64, H_,H_,0><<<gH, blk, SM_H>>>(H1, W2h, W2l, b2, H2,
            nullptr, nullptr, nullptr, nullptr, nullptr, nullptr, tarr, s, 0.f);
        gemm_mma<64,64,32,16, H_,D_,1><<<gD, blk, SM_D>>>(H2, W3h, W3l, b3, A,
            K2, nullptr, nullptr, nullptr, Y, nullptr, tarr, s, 0.5f);
        // eval 3
        gemm_mma<128,128,32,64, D_,H_,0><<<gH, blk, SM_H>>>(A, W1h, W1l, b1, H1,
            nullptr, nullptr, nullptr, nullptr, nullptr, nullptr, tarr, s, 0.f);
        gemm_mma<128,128,32,64, H_,H_,0><<<gH, blk, SM_H>>>(H1, W2h, W2l, b2, H2,
            nullptr, nullptr, nullptr, nullptr, nullptr, nullptr, tarr, s, 0.f);
        gemm_mma<64,64,32,16, H_,D_,1><<<gD, blk, SM_D>>>(H2, W3h, W3l, b3, A,
            K3, nullptr, nullptr, nullptr, Y, nullptr, tarr, s, 1.0f);
        // eval 4 + RK4 combine fused
        gemm_mma<128,128,32,64, D_,H_,0><<<gH, blk, SM_H>>>(A, W1h, W1l, b1, H1,
            nullptr, nullptr, nullptr, nullptr, nullptr, nullptr, tarr, s, 0.f);
        gemm_mma<128,128,32,64, H_,H_,0><<<gH, blk, SM_H>>>(H1, W2h, W2l, b2, H2,
            nullptr, nullptr, nullptr, nullptr, nullptr, nullptr, tarr, s, 0.f);
        gemm_mma<64,64,32,16, H_,D_,2><<<gD, blk, SM_D>>>(H2, W3h, W3l, b3, A,
            nullptr, K1, K2, K3, Y, out, tarr, s, 0.f);
    }
}

// round 7
// speedup vs baseline: 2.8612x; 1.4606x over previous
#include <cuda_runtime.h>
#include <cuda_fp16.h>
#include <cstdint>
#include <cstddef>

#define S_ 4
#define B_ 512
#define D_ 256
#define H_ 1024
#define T_ 50
#define M_ (S_*B_)          // 2048
#define PRED (M_*T_*D_)

// ---------------- device scratch (no allocation allowed) ----------------
__device__ __half g_A [M_*D_];       // layer-1 input (probe state), fp16
__device__ __half g_H1[M_*H_];
__device__ __half g_H2[M_*H_];
__device__ float g_K1[M_*D_], g_K2[M_*D_], g_K3[M_*D_], g_Y[M_*D_];
// weights transposed to [N,K], single fp16
__device__ __half g_W1[H_*D_];
__device__ __half g_W2[H_*H_];
__device__ __half g_W3[D_*H_];

// ---------------- helpers ----------------
__device__ __forceinline__ uint32_t smem_u32(const void* p) {
    uint32_t a;
    asm("{ .reg .u64 t; cvta.to.shared.u64 t, %1; cvt.u32.u64 %0, t; }" : "=r"(a) : "l"(p));
    return a;
}
__device__ __forceinline__ void cp_async16(uint32_t saddr, const void* gaddr) {
    asm volatile("cp.async.cg.shared.global [%0], [%1], 16;" :: "r"(saddr), "l"(gaddr));
}
#define CP_COMMIT() asm volatile("cp.async.commit_group;" ::: "memory")
#define CP_WAIT1()  asm volatile("cp.async.wait_group 1;" ::: "memory")

__device__ __forceinline__ void ldsm_x4(uint32_t* r, uint32_t addr) {
    asm volatile("ldmatrix.sync.aligned.m8n8.x4.shared.b16 {%0,%1,%2,%3}, [%4];"
                 : "=r"(r[0]), "=r"(r[1]), "=r"(r[2]), "=r"(r[3]) : "r"(addr));
}
__device__ __forceinline__ void mma16816(float* c, const uint32_t* a, uint32_t b0, uint32_t b1) {
    asm volatile("mma.sync.aligned.m16n8k16.row.col.f32.f16.f16.f32 "
                 "{%0,%1,%2,%3}, {%4,%5,%6,%7}, {%8,%9}, {%0,%1,%2,%3};"
                 : "+f"(c[0]), "+f"(c[1]), "+f"(c[2]), "+f"(c[3])
                 : "r"(a[0]), "r"(a[1]), "r"(a[2]), "r"(a[3]), "r"(b0), "r"(b1));
}

__device__ __forceinline__ float fast_tanh(float x) {
    float t = __expf(2.0f * x);
    return 1.0f - 2.0f / (t + 1.0f);
}
__device__ __forceinline__ uint32_t pack_h2(float a, float b) {
    __half2 h = __floats2half2_rn(a, b);
    return *reinterpret_cast<uint32_t*>(&h);
}

// ---------------- tensor-core (HMMA fp16) GEMM ----------------
// C[M=2048, NFULL] = A[M,KDIM] @ W^T   (W stored [NFULL,KDIM] fp16)
// per-chunk stage = [A(BM rows) | W(BN rows)], 64 K-elems each.
// 3-stage cp.async pipeline, one __syncthreads + wait_group 1 per chunk.
// EPI 0: tanh -> fp16 -> O
// EPI 1: k=C+bias; Kout=k; probe=Y+alpha*dt*k -> fp16 -> O
// EPI 2: k4=C+bias; y'=Y+dt/6*(K1+2K2+2K3+k4); Y=y'; traj store; fp16(y') -> O
template<int BM, int BN, int WM, int WN, int KDIM, int NFULL, int EPI>
__global__ void __launch_bounds__(256)
gemm_mma(const __half* __restrict__ A,
         const __half* __restrict__ W,
         const float* __restrict__ bias,
         __half* __restrict__ O,
         float* __restrict__ Kout,
         const float* __restrict__ K1c, const float* __restrict__ K2c, const float* __restrict__ K3c,
         float* __restrict__ Ybuf, float* __restrict__ dout,
         const float* __restrict__ tarr, int step, float alpha)
{
    constexpr int WARPS_M = BM / WM;
    constexpr int NC      = KDIM / 64;          // 64-elem K chunks
    constexpr int STAGE   = (BM + BN) * 128;
    constexpr int MI = WM / 16, NJ = WN / 8, NJJ = WN / 16;

    extern __shared__ __align__(128) char sm[];
    const uint32_t smb = smem_u32(sm);

    const int tid  = threadIdx.x;
    const int wid  = tid >> 5, lane = tid & 31;
    const int wm   = wid % WARPS_M, wn = wid / WARPS_M;
    const int bm   = blockIdx.y * BM;
    const int bn   = blockIdx.x * BN;

    float acc[MI][NJ][4];
    #pragma unroll
    for (int i = 0; i < MI; i++)
        #pragma unroll
        for (int j = 0; j < NJ; j++)
            #pragma unroll
            for (int q = 0; q < 4; q++) acc[i][j][q] = 0.0f;

    auto load_chunk = [&](int c, int slot) {
        const int k0 = c * 64;
        const uint32_t sb = smb + (uint32_t)slot * STAGE;
        #pragma unroll
        for (int i = tid; i < (BM + BN) * 8; i += 256) {
            const int seg = i & 7;
            const bool isA = i < BM * 8;
            const int row  = (isA ? i : i - BM * 8) >> 3;
            const __half* src = isA
                ? A + (size_t)(bm + row) * KDIM + k0 + seg * 8
                : W + (size_t)(bn + row) * KDIM + k0 + seg * 8;
            const uint32_t base = sb + (uint32_t)((isA ? row : BM + row)) * 128;
            cp_async16(base + (uint32_t)((seg ^ (row & 7)) << 4), src);
        }
    };

    // prologue: 2 stages in flight
    load_chunk(0, 0); CP_COMMIT();
    load_chunk(1, 1); CP_COMMIT();

    const int oct = lane >> 3, lr = lane & 7;

    for (int c = 0; c < NC; c++) {
        CP_WAIT1();            // chunk c complete (chunk c+1 may be in flight)
        __syncthreads();       // all warps done reading stage (c-1)%3
        if (c + 2 < NC) load_chunk(c + 2, (c + 2) % 3);
        CP_COMMIT();           // commit every iter (possibly empty) — uniform group algebra

        const uint32_t sb = smb + (uint32_t)(c % 3) * STAGE;
        const uint32_t Ab = sb;
        const uint32_t Bb = sb + BM * 128;

        #pragma unroll
        for (int t = 0; t < 4; t++) {
            uint32_t af[MI][4], bf[NJJ][4];
            #pragma unroll
            for (int i = 0; i < MI; i++) {
                const int row = wm * WM + i * 16 + (oct & 1) * 8 + lr;
                const int ks  = t * 2 + (oct >> 1);
                ldsm_x4(af[i], Ab + (uint32_t)row * 128 + (uint32_t)((ks ^ (row & 7)) << 4));
            }
            #pragma unroll
            for (int jj = 0; jj < NJJ; jj++) {
                const int row = wn * WN + jj * 16 + (oct >> 1) * 8 + lr;
                const int ks  = t * 2 + (oct & 1);
                ldsm_x4(bf[jj], Bb + (uint32_t)row * 128 + (uint32_t)((ks ^ (row & 7)) << 4));
            }
            #pragma unroll
            for (int i = 0; i < MI; i++)
                #pragma unroll
                for (int j = 0; j < NJ; j++)
                    mma16816(acc[i][j], af[i], bf[j >> 1][(j & 1) * 2], bf[j >> 1][(j & 1) * 2 + 1]);
        }
    }

    // ---------------- fused epilogue ----------------
    float dt = 0.0f;
    if (EPI != 0) dt = tarr[step + 1] - tarr[step];
    const float ad = alpha * dt;
    const float c6 = dt * (1.0f / 6.0f);

    const int r00   = bm + wm * WM + (lane >> 2);
    const int cbase = bn + wn * WN + (lane & 3) * 2;

    #pragma unroll
    for (int i = 0; i < MI; i++) {
        #pragma unroll
        for (int j = 0; j < NJ; j++) {
            const int cc = cbase + j * 8;
            const float2 bs = *(const float2*)&bias[cc];
            const int rows[2] = { r00 + i * 16, r00 + i * 16 + 8 };
            #pragma unroll
            for (int h = 0; h < 2; h++) {
                float v0 = acc[i][j][2*h + 0] + bs.x;
                float v1 = acc[i][j][2*h + 1] + bs.y;
                const size_t idx = (size_t)rows[h] * NFULL + cc;
                if (EPI == 0) {
                    v0 = fast_tanh(v0); v1 = fast_tanh(v1);
                    *(uint32_t*)(O + idx) = pack_h2(v0, v1);
                } else if (EPI == 1) {
                    *(float2*)&Kout[idx] = make_float2(v0, v1);
                    const float2 y = *(const float2*)&Ybuf[idx];
                    *(uint32_t*)(O + idx) = pack_h2(fmaf(ad, v0, y.x), fmaf(ad, v1, y.y));
                } else {
                    const float2 y  = *(const float2*)&Ybuf[idx];
                    const float2 k1 = *(const float2*)&K1c[idx];
                    const float2 k2 = *(const float2*)&K2c[idx];
                    const float2 k3 = *(const float2*)&K3c[idx];
                    const float y0 = y.x + c6 * (k1.x + 2.0f*k2.x + 2.0f*k3.x + v0);
                    const float y1 = y.y + c6 * (k1.y + 2.0f*k2.y + 2.0f*k3.y + v1);
                    *(float2*)&Ybuf[idx] = make_float2(y0, y1);
                    *(float2*)&dout[((size_t)rows[h] * T_ + step + 1) * NFULL + cc] =
                        make_float2(y0, y1);
                    *(uint32_t*)(O + idx) = pack_h2(y0, y1);
                }
            }
        }
    }
}

// ---------------- weight prep: W[K,N] fp32 -> Wt[N,K] fp16 ----------------
__global__ void prep_w(const float* __restrict__ W,
                       __half* __restrict__ Wt, int K, int N)
{
    __shared__ float s[32][33];
    int k0 = blockIdx.y * 32, n0 = blockIdx.x * 32;
    int tx = threadIdx.x, ty = threadIdx.y;   // (32,8)
    #pragma unroll
    for (int r = 0; r < 4; r++)
        s[ty + r*8][tx] = W[(size_t)(k0 + ty + r*8) * N + n0 + tx];
    __syncthreads();
    #pragma unroll
    for (int r = 0; r < 4; r++) {
        int n = n0 + ty + r*8;
        Wt[(size_t)n * K + k0 + tx] = __float2half_rn(s[tx][ty + r*8]);
    }
}

__global__ void init_k(const float* __restrict__ fp, float* __restrict__ out) {
    int i = blockIdx.x * blockDim.x + threadIdx.x;
    if (i < M_ * D_) {
        float v = fp[i];
        g_Y[i] = v;
        g_A[i] = __float2half_rn(v);
        int m = i >> 8, d = i & 255;
        out[(size_t)m * T_ * D_ + d] = v;
    }
}

__global__ void tail_k(float* __restrict__ out, int out_size) {
    int i = PRED + blockIdx.x * blockDim.x + threadIdx.x;
    if (i < out_size) out[i] = 0.0f;
}

// ---------------- host ----------------
template<typename T> static T* sym(const void* s) {
    void* p = nullptr;
    cudaGetSymbolAddress(&p, s);
    return (T*)p;
}

extern "C" void kernel_launch(void* const* d_in, const int* in_sizes, int n_in,
                              void* d_out, int out_size)
{
    const float* fp   = (const float*)d_in[0];
    const float* tarr = (const float*)d_in[1];
    const float* W1   = (const float*)d_in[2];
    const float* b1   = (const float*)d_in[3];
    const float* W2   = (const float*)d_in[4];
    const float* b2   = (const float*)d_in[5];
    const float* W3   = (const float*)d_in[6];
    const float* b3   = (const float*)d_in[7];
    float* out = (float*)d_out;
    (void)in_sizes; (void)n_in;

    __half *A  = sym<__half>(g_A);
    __half *H1 = sym<__half>(g_H1), *H2 = sym<__half>(g_H2);
    __half *W1t = sym<__half>(g_W1), *W2t = sym<__half>(g_W2), *W3t = sym<__half>(g_W3);
    float *K1 = sym<float>(g_K1), *K2 = sym<float>(g_K2), *K3 = sym<float>(g_K3);
    float *Y  = sym<float>(g_Y);

    // SMEM: 3 stages of (BM+BN)*128 bytes
    constexpr int SM_H = 3 * (128 + 128) * 128;  // 98304 (H layers)
    constexpr int SM_D = 3 * (64 + 64) * 128;    // 49152 (L3)
    cudaFuncSetAttribute((const void*)gemm_mma<128,128,32,64, D_,H_,0>,
                         cudaFuncAttributeMaxDynamicSharedMemorySize, SM_H);
    cudaFuncSetAttribute((const void*)gemm_mma<128,128,32,64, H_,H_,0>,
                         cudaFuncAttributeMaxDynamicSharedMemorySize, SM_H);
    cudaFuncSetAttribute((const void*)gemm_mma<64,64,32,16, H_,D_,1>,
                         cudaFuncAttributeMaxDynamicSharedMemorySize, SM_D);
    cudaFuncSetAttribute((const void*)gemm_mma<64,64,32,16, H_,D_,2>,
                         cudaFuncAttributeMaxDynamicSharedMemorySize, SM_D);

    // small kernels first (also shifts profiler capture toward a GEMM)
    init_k<<<(M_*D_ + 255)/256, 256>>>(fp, out);
    if (out_size > PRED)
        tail_k<<<(out_size - PRED + 255)/256, 256>>>(out, out_size);
    prep_w<<<dim3(H_/32, D_/32), dim3(32,8)>>>(W1, W1t, D_, H_);
    prep_w<<<dim3(H_/32, H_/32), dim3(32,8)>>>(W2, W2t, H_, H_);
    prep_w<<<dim3(D_/32, H_/32), dim3(32,8)>>>(W3, W3t, H_, D_);

    dim3 blk(256);
    dim3 gH(H_/128, M_/128);  // (8,16) = 128 CTAs
    dim3 gD(D_/64,  M_/64);   // (4,32) = 128 CTAs

    for (int s = 0; s < T_ - 1; s++) {
        // eval 1: f(Y)
        gemm_mma<128,128,32,64, D_,H_,0><<<gH, blk, SM_H>>>(A, W1t, b1, H1,
            nullptr, nullptr, nullptr, nullptr, nullptr, nullptr, tarr, s, 0.f);
        gemm_mma<128,128,32,64, H_,H_,0><<<gH, blk, SM_H>>>(H1, W2t, b2, H2,
            nullptr, nullptr, nullptr, nullptr, nullptr, nullptr, tarr, s, 0.f);
        gemm_mma<64,64,32,16, H_,D_,1><<<gD, blk, SM_D>>>(H2, W3t, b3, A,
            K1, nullptr, nullptr, nullptr, Y, nullptr, tarr, s, 0.5f);
        // eval 2
        gemm_mma<128,128,32,64, D_,H_,0><<<gH, blk, SM_H>>>(A, W1t, b1, H1,
            nullptr, nullptr, nullptr, nullptr, nullptr, nullptr, tarr, s, 0.f);
        gemm_mma<128,128,32,64, H_,H_,0><<<gH, blk, SM_H>>>(H1, W2t, b2, H2,
            nullptr, nullptr, nullptr, nullptr, nullptr, nullptr, tarr, s, 0.f);
        gemm_mma<64,64,32,16, H_,D_,1><<<gD, blk, SM_D>>>(H2, W3t, b3, A,
            K2, nullptr, nullptr, nullptr, Y, nullptr, tarr, s, 0.5f);
        // eval 3
        gemm_mma<128,128,32,64, D_,H_,0><<<gH, blk, SM_H>>>(A, W1t, b1, H1,
            nullptr, nullptr, nullptr, nullptr, nullptr, nullptr, tarr, s, 0.f);
        gemm_mma<128,128,32,64, H_,H_,0><<<gH, blk, SM_H>>>(H1, W2t, b2, H2,
            nullptr, nullptr, nullptr, nullptr, nullptr, nullptr, tarr, s, 0.f);
        gemm_mma<64,64,32,16, H_,D_,1><<<gD, blk, SM_D>>>(H2, W3t, b3, A,
            K3, nullptr, nullptr, nullptr, Y, nullptr, tarr, s, 1.0f);
        // eval 4 + RK4 combine fused
        gemm_mma<128,128,32,64, D_,H_,0><<<gH, blk, SM_H>>>(A, W1t, b1, H1,
            nullptr, nullptr, nullptr, nullptr, nullptr, nullptr, tarr, s, 0.f);
        gemm_mma<128,128,32,64, H_,H_,0><<<gH, blk, SM_H>>>(H1, W2t, b2, H2,
            nullptr, nullptr, nullptr, nullptr, nullptr, nullptr, tarr, s, 0.f);
        gemm_mma<64,64,32,16, H_,D_,2><<<gD, blk, SM_D>>>(H2, W3t, b3, A,
            nullptr, K1, K2, K3, Y, out, tarr, s, 0.f);
    }
}